// round 3
// baseline (speedup 1.0000x reference)
#include <cuda_runtime.h>

#define MAXC 256
#define NT   256
#define TM   64
#define BK   16

// ---------------- device scratch (no allocations allowed) ----------------
__device__ float d_G[MAXC * MAXC];     // gram (upper triangle valid, stride MAXC)
__device__ float d_s[MAXC];            // column sums
__device__ float d_p[MAXC * MAXC];     // layernormed cls_logits (stride NC)
__device__ float d_sim[MAXC * MAXC];   // p @ p^T (stride MAXC)
__device__ int   d_gstart[MAXC + 1];   // group member offsets
__device__ int   d_members[MAXC];      // member lists sorted by group

// packed f32x2 FMA (2 fp32 MACs per lane-op; ptxas never emits FFMA2 from C++)
union F2U { float2 f; unsigned long long u; };
__device__ __forceinline__ float2 ffma2f(float2 a, float2 b, float2 c) {
    F2U A, B, Cv, D;
    A.f = a; B.f = b; Cv.f = c;
    asm("fma.rn.f32x2 %0, %1, %2, %3;" : "=l"(D.u) : "l"(A.u), "l"(B.u), "l"(Cv.u));
    return D.f;
}

// ---------------- kernel 1: zero scratch ----------------
__global__ void init_kernel() {
    int t = blockIdx.x * NT + threadIdx.x;
    if (t < MAXC * MAXC) d_G[t] = 0.f;
    if (t < MAXC)        d_s[t] = 0.f;
}

// ---------------- kernel 2: layernorm rows of cls_logits ----------------
__global__ void ln_kernel(const float* __restrict__ cls, int C, int NC) {
    int i = threadIdx.x;
    if (i >= C) return;
    const float* x = cls + (size_t)i * NC;
    float mu = 0.f;
    for (int k = 0; k < NC; k++) mu += x[k];
    mu /= (float)NC;
    float var = 0.f;
    for (int k = 0; k < NC; k++) { float d = x[k] - mu; var += d * d; }
    var /= (float)NC;
    float inv = 1.0f / sqrtf(var + 1e-5f);
    float* p = d_p + (size_t)i * NC;
    for (int k = 0; k < NC; k++) p[k] = (x[k] - mu) * inv;
}

// ---------------- kernel 3: sim = p @ p^T ----------------
__global__ void sim_kernel(int C, int NC) {
    extern __shared__ float ps[];
    int i = blockIdx.x;
    for (int k = threadIdx.x; k < NC; k += NT) ps[k] = d_p[(size_t)i * NC + k];
    __syncthreads();
    int j = threadIdx.x;
    if (j < C) {
        const float* pj = d_p + (size_t)j * NC;
        float acc = 0.f;
        for (int k = 0; k < NC; k++) acc = fmaf(ps[k], pj[k], acc);
        d_sim[i * MAXC + j] = acc;
    }
}

// ---------------- kernel 4: gram = M^T M (split-K, sym tiles, f32x2) -----
// grid.x = tile-pair (ti<=tj), grid.y = K chunk. Column sums fused into
// diagonal tiles. 256 thr as 16x16, each computes 4x4 of a 64x64 tile.
__global__ void gram_kernel(const float* __restrict__ M, int P, int C, int L, int nt) {
    __shared__ __align__(16) float As[BK][TM];
    __shared__ __align__(16) float Bs[BK][TM];

    int tp = blockIdx.x;
    int ti = 0, rr = tp;
    while (rr >= nt - ti) { rr -= (nt - ti); ti++; }
    int tj = ti + rr;

    int k0 = blockIdx.y * L;
    if (k0 >= P) return;
    int kend = min(k0 + L, P);

    int tid  = threadIdx.x;
    int loadc = tid & 63;
    int loadk = tid >> 6;
    int cA = ti * TM + loadc;
    int cB = tj * TM + loadc;
    bool diag = (ti == tj);
    float csum = 0.f;

    int tx = tid & 15, ty = tid >> 4;
    float2 acc[4][2];
#pragma unroll
    for (int i = 0; i < 4; i++) {
        acc[i][0] = make_float2(0.f, 0.f);
        acc[i][1] = make_float2(0.f, 0.f);
    }

    for (int k = k0; k < kend; k += BK) {
#pragma unroll
        for (int u = 0; u < 4; u++) {
            int kk = loadk + u * 4;
            int p  = k + kk;
            bool pin = (p < kend);
            float va = (pin && cA < C) ? __ldg(&M[(size_t)p * C + cA]) : 0.f;
            As[kk][loadc] = va;
            if (diag) {
                csum += va;
            } else {
                float vb = (pin && cB < C) ? __ldg(&M[(size_t)p * C + cB]) : 0.f;
                Bs[kk][loadc] = vb;
            }
        }
        __syncthreads();
#pragma unroll
        for (int kk = 0; kk < BK; kk++) {
            const float* brow = diag ? As[kk] : Bs[kk];
            float4 bv = *(const float4*)(brow + tx * 4);
            float4 av = *(const float4*)(As[kk] + ty * 4);
            float2 b01 = make_float2(bv.x, bv.y);
            float2 b23 = make_float2(bv.z, bv.w);
            float aa[4] = {av.x, av.y, av.z, av.w};
#pragma unroll
            for (int i = 0; i < 4; i++) {
                float2 ai = make_float2(aa[i], aa[i]);
                acc[i][0] = ffma2f(ai, b01, acc[i][0]);
                acc[i][1] = ffma2f(ai, b23, acc[i][1]);
            }
        }
        __syncthreads();
    }

#pragma unroll
    for (int i = 0; i < 4; i++) {
        int gi = ti * TM + ty * 4 + i;
        if (gi >= C) continue;
        float vals[4] = {acc[i][0].x, acc[i][0].y, acc[i][1].x, acc[i][1].y};
#pragma unroll
        for (int jj = 0; jj < 4; jj++) {
            int gj = tj * TM + tx * 4 + jj;
            if (gj < C) atomicAdd(&d_G[gi * MAXC + gj], vals[jj]);
        }
    }
    if (diag && cA < C) atomicAdd(&d_s[cA], csum);
}

// ---------------- kernel 5: greedy association + group build ------------
// Single CTA. cond packed to bits in smem, then a 1-warp serial scan.
__global__ void assoc_kernel(float* __restrict__ out, int C) {
    __shared__ unsigned cw[MAXC * (MAXC / 32)];
    __shared__ unsigned aw[MAXC / 32];
    __shared__ int lab[MAXC];
    __shared__ int cnt[MAXC];
    __shared__ int gs[MAXC + 1];
    __shared__ int mem[MAXC];
    int tid = threadIdx.x;
    int nw  = (C + 31) >> 5;

    for (int t = tid; t < MAXC * (MAXC / 32); t += NT) cw[t] = 0u;
    if (tid < MAXC) lab[tid] = -1;
    if (tid < (MAXC / 32)) aw[tid] = 0u;
    __syncthreads();

    // build cond bits: dice > 0.4 && sim > 0.5
    for (int idx = tid; idx < C * C; idx += NT) {
        int i = idx / C, j = idx - i * C;
        if (d_sim[i * MAXC + j] > 0.5f) {
            int lo = i < j ? i : j, hi = i < j ? j : i;
            if (2.f * d_G[lo * MAXC + hi] > 0.4f * (d_s[i] + d_s[j]))
                atomicOr(&cw[i * (MAXC / 32) + (j >> 5)], 1u << (j & 31));
        }
    }
    __syncthreads();

    // warp-0 serial greedy scan (matches jax.lax.scan semantics)
    if (tid < 32) {
        int l = tid;
        for (int i = 0; i < C; i++) {
            bool skip = (aw[i >> 5] >> (i & 31)) & 1u;
            if (!skip && l < nw) {
                unsigned take = cw[i * (MAXC / 32) + l] & ~aw[l];
                if (take) {
                    unsigned t2 = take;
                    while (t2) { int b = __ffs(t2) - 1; lab[l * 32 + b] = i; t2 &= t2 - 1; }
                    aw[l] |= take;
                }
            }
            __syncwarp();
        }
    }
    __syncthreads();

    // group counts / member lists
    if (tid < C) {
        int c0 = 0;
        for (int j = 0; j < C; j++) if (lab[j] == tid) c0++;
        cnt[tid] = c0;
    }
    __syncthreads();
    if (tid == 0) {
        gs[0] = 0;
        for (int g = 0; g < C; g++) gs[g + 1] = gs[g] + cnt[g];
    }
    __syncthreads();
    if (tid < C) {
        int pos = gs[tid];
        for (int j = 0; j < C; j++) if (lab[j] == tid) mem[pos++] = j;
        out[tid]     = (float)lab[tid];                 // labels
        out[C + tid] = cnt[tid] > 0 ? 1.f : 0.f;        // group_valid
        d_gstart[tid] = gs[tid];
        if (tid == 0) d_gstart[C] = gs[C];
    }
    __syncthreads();
    int total = gs[C];
    for (int m = tid; m < total; m += NT) d_members[m] = mem[m];
}

// ---------------- kernel 6: per-group segment-max over mask columns -----
__global__ void merge_masks_kernel(const float* __restrict__ M, float* __restrict__ dstbase,
                                   int P, int C, int TR) {
    extern __shared__ float Ms[];
    __shared__ int gs[MAXC + 1];
    __shared__ int mem[MAXC];
    int base = blockIdx.x * TR;
    int nr = P - base; if (nr > TR) nr = TR;
    int tot = nr * C;
    const float* src = M + (size_t)base * C;
    for (int idx = threadIdx.x; idx < tot; idx += NT) Ms[idx] = src[idx];
    for (int t = threadIdx.x; t <= C; t += NT) gs[t] = d_gstart[t];
    for (int t = threadIdx.x; t < C; t += NT) mem[t] = d_members[t];
    __syncthreads();

    float* dst = dstbase + (size_t)base * C;
    int pl = 0, g = threadIdx.x;
    while (g >= C) { g -= C; pl++; }
    for (int idx = threadIdx.x; idx < tot; idx += NT) {
        int beg = gs[g], end = gs[g + 1];
        float v = 0.f;
        if (end > beg) {
            v = Ms[pl * C + mem[beg]];
            for (int m = beg + 1; m < end; m++) v = fmaxf(v, Ms[pl * C + mem[m]]);
        }
        dst[idx] = v;
        g += NT;
        while (g >= C) { g -= C; pl++; }
    }
}

// ---------------- kernel 7: per-group segment-max over cls rows ---------
__global__ void merge_cls_kernel(const float* __restrict__ cls, float* __restrict__ outc,
                                 int C, int NC) {
    int g = blockIdx.x;
    int beg = d_gstart[g], end = d_gstart[g + 1];
    for (int k = threadIdx.x; k < NC; k += NT) {
        float v = 0.f;
        if (end > beg) {
            v = cls[(size_t)d_members[beg] * NC + k];
            for (int m = beg + 1; m < end; m++)
                v = fmaxf(v, cls[(size_t)d_members[m] * NC + k]);
        }
        outc[(size_t)g * NC + k] = v;
    }
}

// ---------------- host ----------------
extern "C" void kernel_launch(void* const* d_in, const int* in_sizes, int n_in,
                              void* d_out, int out_size) {
    const float* M   = (const float*)d_in[0];   // [P, C]
    const float* cls = (const float*)d_in[1];   // [C, NC]
    int C  = in_sizes[2];
    int NC = in_sizes[1] / C;
    int P  = in_sizes[0] / C;

    float* out       = (float*)d_out;
    float* out_masks = out + 2 * (size_t)C;
    float* out_cls   = out_masks + (size_t)P * C;

    init_kernel<<<(MAXC * MAXC + NT - 1) / NT, NT>>>();
    ln_kernel<<<1, NT>>>(cls, C, NC);
    sim_kernel<<<C, NT, NC * sizeof(float)>>>(C, NC);

    int nt  = (C + TM - 1) / TM;
    int NTP = nt * (nt + 1) / 2;
    int KS  = 64;
    int L   = ((P + KS - 1) / KS + BK - 1) / BK * BK;
    dim3 ggrid(NTP, KS);
    gram_kernel<<<ggrid, NT>>>(M, P, C, L, nt);

    assoc_kernel<<<1, NT>>>(out, C);

    int TR2 = 45000 / (4 * C);
    if (TR2 > 64) TR2 = 64;
    if (TR2 < 1)  TR2 = 1;
    int NB2 = (P + TR2 - 1) / TR2;
    merge_masks_kernel<<<NB2, NT, (size_t)TR2 * C * sizeof(float)>>>(M, out_masks, P, C, TR2);
    merge_cls_kernel<<<C, NT>>>(cls, out_cls, C, NC);
}

// round 6
// speedup vs baseline: 1.6133x; 1.6133x over previous
#include <cuda_runtime.h>
#include <cuda_bf16.h>
#include <cstdint>

#define MAXC  256
#define NT    256
#define NCTA  148
#define NTG   320          // 10 warps: one 64x64 subtile each
#define LKC   64           // k-rows per chunk

// ---------------- device scratch (no allocations allowed) ----------------
__device__ float d_G[MAXC * MAXC];     // gram (stride MAXC)
__device__ float d_s[MAXC];            // column sums
__device__ float d_p[MAXC * MAXC];     // layernormed cls_logits (stride NC)
__device__ float d_sim[MAXC * MAXC];   // p @ p^T (stride MAXC)
__device__ int   d_gstart[MAXC + 1];   // group member offsets
__device__ int   d_members[MAXC];      // member lists sorted by group
__device__ float d_part[(size_t)NCTA * 10 * 4096];  // split-K partials (~24MB)

// ---------------- kernel 1: zero d_s ----------------
__global__ void init_s_kernel() {
    if (threadIdx.x < MAXC) d_s[threadIdx.x] = 0.f;
}

// ---------------- kernel 2: layernorm rows of cls_logits ----------------
__global__ void ln_kernel(const float* __restrict__ cls, int C, int NC) {
    int i = threadIdx.x;
    if (i >= C) return;
    const float* x = cls + (size_t)i * NC;
    float mu = 0.f;
    for (int k = 0; k < NC; k++) mu += x[k];
    mu /= (float)NC;
    float var = 0.f;
    for (int k = 0; k < NC; k++) { float d = x[k] - mu; var += d * d; }
    var /= (float)NC;
    float inv = 1.0f / sqrtf(var + 1e-5f);
    float* p = d_p + (size_t)i * NC;
    for (int k = 0; k < NC; k++) p[k] = (x[k] - mu) * inv;
}

// ---------------- kernel 3: sim = p @ p^T ----------------
__global__ void sim_kernel(int C, int NC) {
    extern __shared__ float ps[];
    int i = blockIdx.x;
    for (int k = threadIdx.x; k < NC; k += NT) ps[k] = d_p[(size_t)i * NC + k];
    __syncthreads();
    int j = threadIdx.x;
    if (j < C) {
        const float* pj = d_p + (size_t)j * NC;
        float acc = 0.f;
        for (int k = 0; k < NC; k++) acc = fmaf(ps[k], pj[k], acc);
        d_sim[i * MAXC + j] = acc;
    }
}

// ---------------- kernel 4: gram = M^T M via mma.sync bf16 --------------
// 148 persistent CTAs, 10 warps each. Per chunk of 64 k-rows: threads<200
// transpose-stage M into smem T[256][66] bf16 (pad 66 => conflict-free).
// Each warp owns one 64x64 upper-triangle subtile, accumulating fp32 via
// mma.sync.m16n8k16 (sm_103-legal; no 'a'-suffix features).
__device__ __forceinline__ void mma16816(float* d, const uint32_t* a, const uint32_t* b) {
    asm volatile(
        "mma.sync.aligned.m16n8k16.row.col.f32.bf16.bf16.f32 "
        "{%0,%1,%2,%3}, {%4,%5,%6,%7}, {%8,%9}, {%0,%1,%2,%3};"
        : "+f"(d[0]), "+f"(d[1]), "+f"(d[2]), "+f"(d[3])
        : "r"(a[0]), "r"(a[1]), "r"(a[2]), "r"(a[3]), "r"(b[0]), "r"(b[1]));
}

__global__ __launch_bounds__(NTG, 1)
void gram_mma_kernel(const float* __restrict__ M, int P, int C, int Lk) {
    __shared__ __nv_bfloat16 T[256 * 66];

    int tid = threadIdx.x, wid = tid >> 5, lane = tid & 31;
    int gid = lane >> 2, tig = lane & 3;

    const unsigned char TIa[10] = {0,0,0,0,1,1,1,2,2,3};
    const unsigned char TJa[10] = {0,1,2,3,1,2,3,2,3,3};
    int ti = TIa[wid], tj = TJa[wid];

    float acc[4][8][4];
#pragma unroll
    for (int mb = 0; mb < 4; mb++)
#pragma unroll
        for (int nb = 0; nb < 8; nb++)
#pragma unroll
            for (int q = 0; q < 4; q++) acc[mb][nb][q] = 0.f;

    size_t kbeg = (size_t)blockIdx.x * (size_t)Lk;
    size_t kend = kbeg + (size_t)Lk;
    if (kend > (size_t)P) kend = (size_t)P;

    bool cv = (tid < C);
    float colsum = 0.f;

    for (size_t k0 = kbeg; k0 < kend; k0 += LKC) {
        // ---- stage chunk: global fp32 -> smem bf16, transposed ----
        if (cv) {
            const float* bp = M + k0 * (size_t)C + tid;
            size_t rem = kend - k0;
#pragma unroll 8
            for (int k = 0; k < LKC; k += 2) {
                float a = 0.f, b = 0.f;
                if ((size_t)k < rem)     a = __ldg(bp + (size_t)k * C);
                if ((size_t)k + 1 < rem) b = __ldg(bp + ((size_t)k + 1) * C);
                colsum += a + b;
                uint32_t pk;
                asm("cvt.rn.satfinite.bf16x2.f32 %0, %1, %2;" : "=r"(pk) : "f"(b), "f"(a));
                *(uint32_t*)&T[tid * 66 + k] = pk;
            }
        }
        __syncthreads();

        // ---- 4 k-steps of 16 ----
#pragma unroll
        for (int ks = 0; ks < 4; ks++) {
            int kb = ks * 16;
            uint32_t a[4][4], b[8][2];
            int klo = kb + tig * 2, khi = kb + 8 + tig * 2;
#pragma unroll
            for (int mb = 0; mb < 4; mb++) {
                int r0 = ti * 64 + mb * 16 + gid;
                a[mb][0] = *(const uint32_t*)&T[r0 * 66 + klo];
                a[mb][1] = *(const uint32_t*)&T[(r0 + 8) * 66 + klo];
                a[mb][2] = *(const uint32_t*)&T[r0 * 66 + khi];
                a[mb][3] = *(const uint32_t*)&T[(r0 + 8) * 66 + khi];
            }
#pragma unroll
            for (int nb = 0; nb < 8; nb++) {
                int n0 = tj * 64 + nb * 8 + gid;
                b[nb][0] = *(const uint32_t*)&T[n0 * 66 + klo];
                b[nb][1] = *(const uint32_t*)&T[n0 * 66 + khi];
            }
#pragma unroll
            for (int mb = 0; mb < 4; mb++)
#pragma unroll
                for (int nb = 0; nb < 8; nb++)
                    mma16816(acc[mb][nb], a[mb], b[nb]);
        }
        __syncthreads();
    }

    if (cv) atomicAdd(&d_s[tid], colsum);

    // ---- epilogue: per-CTA partial subtile to d_part ----
    float* dst = d_part + ((size_t)blockIdx.x * 10 + wid) * 4096;
#pragma unroll
    for (int mb = 0; mb < 4; mb++) {
        int r = mb * 16 + gid;
#pragma unroll
        for (int nb = 0; nb < 8; nb++) {
            int cb = nb * 8 + tig * 2;
            *(float2*)(dst + r * 64 + cb)       = make_float2(acc[mb][nb][0], acc[mb][nb][1]);
            *(float2*)(dst + (r + 8) * 64 + cb) = make_float2(acc[mb][nb][2], acc[mb][nb][3]);
        }
    }
}

// ---------------- kernel 5: reduce split-K partials into d_G ------------
__global__ void reduce_gram_kernel(int C) {
    int idx = blockIdx.x * NT + threadIdx.x;
    if (idx >= C * C) return;
    int i = idx / C, j = idx - (idx / C) * C;
    int ti = i >> 6, tj = j >> 6, m, n;
    if (ti <= tj) { m = i & 63; n = j & 63; }
    else { int t = ti; ti = tj; tj = t; m = j & 63; n = i & 63; }
    int st = ti * 4 - (ti * (ti + 1)) / 2 + tj;
    const float* src = d_part + (size_t)st * 4096 + m * 64 + n;
    float acc = 0.f;
#pragma unroll 4
    for (int cta = 0; cta < NCTA; cta++) acc += src[(size_t)cta * 10 * 4096];
    d_G[i * MAXC + j] = acc;
}

// ---------------- kernel 6: greedy association + group build ------------
__global__ void assoc_kernel(float* __restrict__ out, int C) {
    __shared__ unsigned cw[MAXC * (MAXC / 32)];
    __shared__ unsigned aw[MAXC / 32];
    __shared__ int lab[MAXC];
    __shared__ int cnt[MAXC];
    __shared__ int gs[MAXC + 1];
    __shared__ int mem[MAXC];
    int tid = threadIdx.x;
    int nw  = (C + 31) >> 5;

    for (int t = tid; t < MAXC * (MAXC / 32); t += NT) cw[t] = 0u;
    if (tid < MAXC) lab[tid] = -1;
    if (tid < (MAXC / 32)) aw[tid] = 0u;
    __syncthreads();

    for (int idx = tid; idx < C * C; idx += NT) {
        int i = idx / C, j = idx - i * C;
        if (d_sim[i * MAXC + j] > 0.5f) {
            int lo = i < j ? i : j, hi = i < j ? j : i;
            if (2.f * d_G[lo * MAXC + hi] > 0.4f * (d_s[i] + d_s[j]))
                atomicOr(&cw[i * (MAXC / 32) + (j >> 5)], 1u << (j & 31));
        }
    }
    __syncthreads();

    if (tid < 32) {
        int l = tid;
        for (int i = 0; i < C; i++) {
            bool skip = (aw[i >> 5] >> (i & 31)) & 1u;
            if (!skip && l < nw) {
                unsigned take = cw[i * (MAXC / 32) + l] & ~aw[l];
                if (take) {
                    unsigned t2 = take;
                    while (t2) { int b = __ffs(t2) - 1; lab[l * 32 + b] = i; t2 &= t2 - 1; }
                    aw[l] |= take;
                }
            }
            __syncwarp();
        }
    }
    __syncthreads();

    if (tid < C) {
        int c0 = 0;
        for (int j = 0; j < C; j++) if (lab[j] == tid) c0++;
        cnt[tid] = c0;
    }
    __syncthreads();
    if (tid == 0) {
        gs[0] = 0;
        for (int g = 0; g < C; g++) gs[g + 1] = gs[g] + cnt[g];
    }
    __syncthreads();
    if (tid < C) {
        int pos = gs[tid];
        for (int j = 0; j < C; j++) if (lab[j] == tid) mem[pos++] = j;
        out[tid]     = (float)lab[tid];
        out[C + tid] = cnt[tid] > 0 ? 1.f : 0.f;
        d_gstart[tid] = gs[tid];
        if (tid == 0) d_gstart[C] = gs[C];
    }
    __syncthreads();
    int total = gs[C];
    for (int m = tid; m < total; m += NT) d_members[m] = mem[m];
}

// ---------------- kernel 7: per-group segment-max over mask columns -----
__global__ void merge_masks_kernel(const float* __restrict__ M, float* __restrict__ dstbase,
                                   int P, int C, int TR) {
    extern __shared__ float Ms[];
    __shared__ int gs[MAXC + 1];
    __shared__ int mem[MAXC];
    int base = blockIdx.x * TR;
    int nr = P - base; if (nr > TR) nr = TR;
    int tot = nr * C;
    const float* src = M + (size_t)base * C;
    for (int idx = threadIdx.x; idx < tot; idx += NT) Ms[idx] = src[idx];
    for (int t = threadIdx.x; t <= C; t += NT) gs[t] = d_gstart[t];
    for (int t = threadIdx.x; t < C; t += NT) mem[t] = d_members[t];
    __syncthreads();

    float* dst = dstbase + (size_t)base * C;
    int pl = 0, g = threadIdx.x;
    while (g >= C) { g -= C; pl++; }
    for (int idx = threadIdx.x; idx < tot; idx += NT) {
        int beg = gs[g], end = gs[g + 1];
        float v = 0.f;
        if (end > beg) {
            v = Ms[pl * C + mem[beg]];
            for (int m = beg + 1; m < end; m++) v = fmaxf(v, Ms[pl * C + mem[m]]);
        }
        dst[idx] = v;
        g += NT;
        while (g >= C) { g -= C; pl++; }
    }
}

// ---------------- kernel 8: per-group segment-max over cls rows ---------
__global__ void merge_cls_kernel(const float* __restrict__ cls, float* __restrict__ outc,
                                 int C, int NC) {
    int g = blockIdx.x;
    int beg = d_gstart[g], end = d_gstart[g + 1];
    for (int k = threadIdx.x; k < NC; k += NT) {
        float v = 0.f;
        if (end > beg) {
            v = cls[(size_t)d_members[beg] * NC + k];
            for (int m = beg + 1; m < end; m++)
                v = fmaxf(v, cls[(size_t)d_members[m] * NC + k]);
        }
        outc[(size_t)g * NC + k] = v;
    }
}

// ---------------- host ----------------
extern "C" void kernel_launch(void* const* d_in, const int* in_sizes, int n_in,
                              void* d_out, int out_size) {
    const float* M   = (const float*)d_in[0];   // [P, C]
    const float* cls = (const float*)d_in[1];   // [C, NC]
    int C  = in_sizes[2];
    int NC = in_sizes[1] / C;
    int P  = in_sizes[0] / C;

    float* out       = (float*)d_out;
    float* out_masks = out + 2 * (size_t)C;
    float* out_cls   = out_masks + (size_t)P * C;

    init_s_kernel<<<1, MAXC>>>();
    ln_kernel<<<1, NT>>>(cls, C, NC);
    sim_kernel<<<C, NT, NC * sizeof(float)>>>(C, NC);

    int Lk = ((P + NCTA - 1) / NCTA + LKC - 1) & ~(LKC - 1);
    gram_mma_kernel<<<NCTA, NTG>>>(M, P, C, Lk);
    reduce_gram_kernel<<<(C * C + NT - 1) / NT, NT>>>(C);

    assoc_kernel<<<1, NT>>>(out, C);

    int TR2 = 45000 / (4 * C);
    if (TR2 > 64) TR2 = 64;
    if (TR2 < 1)  TR2 = 1;
    int NB2 = (P + TR2 - 1) / TR2;
    merge_masks_kernel<<<NB2, NT, (size_t)TR2 * C * sizeof(float)>>>(M, out_masks, P, C, TR2);
    merge_cls_kernel<<<C, NT>>>(cls, out_cls, C, NC);
}

// round 7
// speedup vs baseline: 1.7441x; 1.0811x over previous
#include <cuda_runtime.h>
#include <cuda_bf16.h>
#include <cstdint>

#define MAXC  256
#define NT    256
#define NCTA  148
#define NTG   320          // 10 warps: one 64x64 subtile each
#define LKC   16           // k-rows per chunk (register-prefetched)
#define TSTR  24           // T row stride in bf16 (12 words: conflict-free frags)

// ---------------- device scratch (no allocations allowed) ----------------
__device__ float d_G[MAXC * MAXC];     // gram (stride MAXC)
__device__ float d_s[MAXC];            // column sums
__device__ float d_p[MAXC * MAXC];     // layernormed cls_logits (stride NC)
__device__ float d_sim[MAXC * MAXC];   // p @ p^T (stride MAXC)
__device__ int   d_gstart[MAXC + 1];   // group member offsets
__device__ int   d_members[MAXC];      // member lists sorted by group
__device__ int   d_colmap[MAXC];       // valid-group-first column permutation
__device__ float d_part[(size_t)NCTA * 10 * 4096];  // split-K partials (~24MB)
__device__ float d_scol[(size_t)NCTA * MAXC];       // per-CTA colsum partials

// ---------------- kernel 1: layernorm rows of cls_logits ----------------
__global__ void ln_kernel(const float* __restrict__ cls, int C, int NC) {
    __shared__ float red[4];
    int i = blockIdx.x;
    const float* x = cls + (size_t)i * NC;
    int t = threadIdx.x, lane = t & 31, w = t >> 5;
    float s = 0.f;
    for (int k = t; k < NC; k += 128) s += __ldg(x + k);
#pragma unroll
    for (int o = 16; o; o >>= 1) s += __shfl_xor_sync(~0u, s, o);
    if (!lane) red[w] = s;
    __syncthreads();
    float mu = (red[0] + red[1] + red[2] + red[3]) / (float)NC;
    __syncthreads();
    float v = 0.f;
    for (int k = t; k < NC; k += 128) { float d = __ldg(x + k) - mu; v += d * d; }
#pragma unroll
    for (int o = 16; o; o >>= 1) v += __shfl_xor_sync(~0u, v, o);
    if (!lane) red[w] = v;
    __syncthreads();
    float var = (red[0] + red[1] + red[2] + red[3]) / (float)NC;
    float inv = 1.0f / sqrtf(var + 1e-5f);
    for (int k = t; k < NC; k += 128)
        d_p[(size_t)i * NC + k] = (__ldg(x + k) - mu) * inv;
}

// ---------------- kernel 2: sim = p @ p^T ----------------
__global__ void sim_kernel(int C, int NC) {
    extern __shared__ float ps[];
    int i = blockIdx.x;
    for (int k = threadIdx.x; k < NC; k += NT) ps[k] = d_p[(size_t)i * NC + k];
    __syncthreads();
    int j = threadIdx.x;
    if (j < C) {
        const float* pj = d_p + (size_t)j * NC;
        float acc = 0.f;
        for (int k = 0; k < NC; k++) acc = fmaf(ps[k], pj[k], acc);
        d_sim[i * MAXC + j] = acc;
    }
}

// ---------------- kernel 3: gram = M^T M via mma.sync bf16 --------------
// Conflict-free T stride (12 words) + register-prefetch pipeline: next
// chunk's 16 LDGs are in flight while the current chunk's MMA runs.
__device__ __forceinline__ void mma16816(float* d, const uint32_t* a, const uint32_t* b) {
    asm volatile(
        "mma.sync.aligned.m16n8k16.row.col.f32.bf16.bf16.f32 "
        "{%0,%1,%2,%3}, {%4,%5,%6,%7}, {%8,%9}, {%0,%1,%2,%3};"
        : "+f"(d[0]), "+f"(d[1]), "+f"(d[2]), "+f"(d[3])
        : "r"(a[0]), "r"(a[1]), "r"(a[2]), "r"(a[3]), "r"(b[0]), "r"(b[1]));
}

__global__ __launch_bounds__(NTG, 1)
void gram_mma_kernel(const float* __restrict__ M, int P, int C, int Lk) {
    __shared__ __nv_bfloat16 T[256 * TSTR];

    int tid = threadIdx.x, wid = tid >> 5, lane = tid & 31;
    int gid = lane >> 2, tig = lane & 3;

    const unsigned char TIa[10] = {0,0,0,0,1,1,1,2,2,3};
    const unsigned char TJa[10] = {0,1,2,3,1,2,3,2,3,3};
    int ti = TIa[wid], tj = TJa[wid];

    float acc[4][8][4];
#pragma unroll
    for (int mb = 0; mb < 4; mb++)
#pragma unroll
        for (int nb = 0; nb < 8; nb++)
#pragma unroll
            for (int q = 0; q < 4; q++) acc[mb][nb][q] = 0.f;

    size_t kbeg = (size_t)blockIdx.x * (size_t)Lk;
    size_t kend = kbeg + (size_t)Lk;
    if (kend > (size_t)P) kend = (size_t)P;

    bool cv = (tid < C);
    float colsum = 0.f;

    // zero rows [C,256) once (they feed frag loads for n/m >= C; outputs unused)
    if (!cv && tid < 256) {
        uint2* zr = (uint2*)&T[tid * TSTR];
#pragma unroll
        for (int j = 0; j < 6; j++) zr[j] = make_uint2(0u, 0u);
    }

    const float* basep = M + tid;
    int nch = (kend > kbeg) ? (int)((kend - kbeg + LKC - 1) / LKC) : 0;

    float pf[LKC];
    if (cv && nch > 0) {
#pragma unroll
        for (int i = 0; i < LKC; i++) {
            size_t p = kbeg + (size_t)i;
            pf[i] = (p < kend) ? __ldg(basep + p * (size_t)C) : 0.f;
        }
    }

    for (int chi = 0; chi < nch; chi++) {
        // ---- stage current chunk regs -> smem (uint2 STS) ----
        if (cv) {
            uint32_t pk[8];
#pragma unroll
            for (int j = 0; j < 8; j++) {
                float a = pf[2 * j], b = pf[2 * j + 1];
                colsum += a + b;
                asm("cvt.rn.satfinite.bf16x2.f32 %0, %1, %2;" : "=r"(pk[j]) : "f"(b), "f"(a));
            }
            uint2* Tw = (uint2*)&T[tid * TSTR];
#pragma unroll
            for (int j = 0; j < 4; j++) Tw[j] = make_uint2(pk[2 * j], pk[2 * j + 1]);
        }
        __syncthreads();

        // ---- prefetch next chunk (LDGs overlap the MMA below) ----
        if (cv && chi + 1 < nch) {
            size_t nk = kbeg + (size_t)(chi + 1) * LKC;
#pragma unroll
            for (int i = 0; i < LKC; i++) {
                size_t p = nk + (size_t)i;
                pf[i] = (p < kend) ? __ldg(basep + p * (size_t)C) : 0.f;
            }
        }

        // ---- one k-step of 16 ----
        {
            uint32_t a[4][4], b[8][2];
            int klo = tig * 2, khi = 8 + tig * 2;
#pragma unroll
            for (int mb = 0; mb < 4; mb++) {
                int r0 = ti * 64 + mb * 16 + gid;
                a[mb][0] = *(const uint32_t*)&T[r0 * TSTR + klo];
                a[mb][1] = *(const uint32_t*)&T[(r0 + 8) * TSTR + klo];
                a[mb][2] = *(const uint32_t*)&T[r0 * TSTR + khi];
                a[mb][3] = *(const uint32_t*)&T[(r0 + 8) * TSTR + khi];
            }
#pragma unroll
            for (int nb = 0; nb < 8; nb++) {
                int n0 = tj * 64 + nb * 8 + gid;
                b[nb][0] = *(const uint32_t*)&T[n0 * TSTR + klo];
                b[nb][1] = *(const uint32_t*)&T[n0 * TSTR + khi];
            }
#pragma unroll
            for (int mb = 0; mb < 4; mb++)
#pragma unroll
                for (int nb = 0; nb < 8; nb++)
                    mma16816(acc[mb][nb], a[mb], b[nb]);
        }
        __syncthreads();
    }

    if (tid < MAXC) d_scol[(size_t)blockIdx.x * MAXC + tid] = cv ? colsum : 0.f;

    float* dst = d_part + ((size_t)blockIdx.x * 10 + wid) * 4096;
#pragma unroll
    for (int mb = 0; mb < 4; mb++) {
        int r = mb * 16 + gid;
#pragma unroll
        for (int nb = 0; nb < 8; nb++) {
            int cb = nb * 8 + tig * 2;
            *(float2*)(dst + r * 64 + cb)       = make_float2(acc[mb][nb][0], acc[mb][nb][1]);
            *(float2*)(dst + (r + 8) * 64 + cb) = make_float2(acc[mb][nb][2], acc[mb][nb][3]);
        }
    }
}

// ---------------- kernel 4: reduce split-K partials into d_G + d_s ------
__global__ void reduce_gram_kernel(int C) {
    int idx = blockIdx.x * NT + threadIdx.x;
    if (idx < C) {           // deterministic column-sum reduce
        float a = 0.f;
        for (int cta = 0; cta < NCTA; cta++) a += d_scol[(size_t)cta * MAXC + idx];
        d_s[idx] = a;
    }
    if (idx >= C * C) return;
    int i = idx / C, j = idx - (idx / C) * C;
    int ti = i >> 6, tj = j >> 6, m, n;
    if (ti <= tj) { m = i & 63; n = j & 63; }
    else { int t = ti; ti = tj; tj = t; m = j & 63; n = i & 63; }
    int st = ti * 4 - (ti * (ti + 1)) / 2 + tj;
    const float* src = d_part + (size_t)st * 4096 + m * 64 + n;
    float acc = 0.f;
#pragma unroll 4
    for (int cta = 0; cta < NCTA; cta++) acc += src[(size_t)cta * 10 * 4096];
    d_G[i * MAXC + j] = acc;
}

// ---------------- kernel 5: greedy association + group build ------------
__global__ void assoc_kernel(float* __restrict__ out, int C) {
    __shared__ unsigned cw[MAXC * (MAXC / 32)];
    __shared__ unsigned aw[MAXC / 32];
    __shared__ int lab[MAXC];
    __shared__ int cnt[MAXC];
    __shared__ int gs[MAXC + 1];
    __shared__ int mem[MAXC];
    int tid = threadIdx.x;
    int nw  = (C + 31) >> 5;

    for (int t = tid; t < MAXC * (MAXC / 32); t += NT) cw[t] = 0u;
    if (tid < MAXC) lab[tid] = -1;
    if (tid < (MAXC / 32)) aw[tid] = 0u;
    __syncthreads();

    for (int idx = tid; idx < C * C; idx += NT) {
        int i = idx / C, j = idx - i * C;
        if (d_sim[i * MAXC + j] > 0.5f) {
            int lo = i < j ? i : j, hi = i < j ? j : i;
            if (2.f * d_G[lo * MAXC + hi] > 0.4f * (d_s[i] + d_s[j]))
                atomicOr(&cw[i * (MAXC / 32) + (j >> 5)], 1u << (j & 31));
        }
    }
    __syncthreads();

    if (tid < 32) {
        int l = tid;
        for (int i = 0; i < C; i++) {
            bool skip = (aw[i >> 5] >> (i & 31)) & 1u;
            if (!skip && l < nw) {
                unsigned take = cw[i * (MAXC / 32) + l] & ~aw[l];
                if (take) {
                    unsigned t2 = take;
                    while (t2) { int b = __ffs(t2) - 1; lab[l * 32 + b] = i; t2 &= t2 - 1; }
                    aw[l] |= take;
                }
            }
            __syncwarp();
        }
    }
    __syncthreads();

    if (tid < C) {
        int c0 = 0;
        for (int j = 0; j < C; j++) if (lab[j] == tid) c0++;
        cnt[tid] = c0;
    }
    __syncthreads();
    if (tid == 0) {
        gs[0] = 0;
        for (int g = 0; g < C; g++) gs[g + 1] = gs[g] + cnt[g];
        int pos = 0;
        for (int g = 0; g < C; g++) if (cnt[g] > 0) d_colmap[pos++] = g;
        for (int g = 0; g < C; g++) if (cnt[g] == 0) d_colmap[pos++] = g;
    }
    __syncthreads();
    if (tid < C) {
        int pos = gs[tid];
        for (int j = 0; j < C; j++) if (lab[j] == tid) mem[pos++] = j;
        out[tid]     = (float)lab[tid];
        out[C + tid] = cnt[tid] > 0 ? 1.f : 0.f;
        d_gstart[tid] = gs[tid];
        if (tid == 0) d_gstart[C] = gs[C];
    }
    __syncthreads();
    int total = gs[C];
    for (int m = tid; m < total; m += NT) d_members[m] = mem[m];
}

// ---------------- kernel 6: per-group segment-max over mask columns -----
// Valid groups packed into the first lanes via d_colmap => dense warps do
// the member loads (few LDG instrs); remaining lanes only write zeros.
__global__ void merge_masks_kernel(const float* __restrict__ M, float* __restrict__ dst,
                                   int P, int C) {
    __shared__ int mem[MAXC];
    int t = threadIdx.x;
    for (int k = t; k < C; k += NT) mem[k] = d_members[k];
    __syncthreads();

    int g = -1, beg = 0, end = 0;
    if (t < C) {
        g   = d_colmap[t];
        beg = d_gstart[g];
        end = d_gstart[g + 1];
    }
    bool act = (t < C);

    for (size_t r0 = (size_t)blockIdx.x * 2; r0 < (size_t)P; r0 += (size_t)gridDim.x * 2) {
        size_t r1 = r0 + 1;
        bool h1 = r1 < (size_t)P;
        float v0 = 0.f, v1 = 0.f;
        const float* row0 = M + r0 * C;
        const float* row1 = M + r1 * C;
        for (int m = beg; m < end; m++) {
            int cc = mem[m];
            v0 = fmaxf(v0, __ldg(row0 + cc));
            if (h1) v1 = fmaxf(v1, __ldg(row1 + cc));
        }
        if (act) {
            dst[r0 * C + g] = v0;
            if (h1) dst[r1 * C + g] = v1;
        }
    }
}

// ---------------- kernel 7: per-group segment-max over cls rows ---------
__global__ void merge_cls_kernel(const float* __restrict__ cls, float* __restrict__ outc,
                                 int C, int NC) {
    int g = blockIdx.x;
    int beg = d_gstart[g], end = d_gstart[g + 1];
    for (int k = threadIdx.x; k < NC; k += NT) {
        float v = 0.f;
        if (end > beg) {
            v = cls[(size_t)d_members[beg] * NC + k];
            for (int m = beg + 1; m < end; m++)
                v = fmaxf(v, cls[(size_t)d_members[m] * NC + k]);
        }
        outc[(size_t)g * NC + k] = v;
    }
}

// ---------------- host ----------------
extern "C" void kernel_launch(void* const* d_in, const int* in_sizes, int n_in,
                              void* d_out, int out_size) {
    const float* M   = (const float*)d_in[0];   // [P, C]
    const float* cls = (const float*)d_in[1];   // [C, NC]
    int C  = in_sizes[2];
    int NC = in_sizes[1] / C;
    int P  = in_sizes[0] / C;

    float* out       = (float*)d_out;
    float* out_masks = out + 2 * (size_t)C;
    float* out_cls   = out_masks + (size_t)P * C;

    ln_kernel<<<C, 128>>>(cls, C, NC);
    sim_kernel<<<C, NT, NC * sizeof(float)>>>(C, NC);

    int Lk = ((P + NCTA - 1) / NCTA + LKC - 1) & ~(LKC - 1);
    gram_mma_kernel<<<NCTA, NTG>>>(M, P, C, Lk);
    reduce_gram_kernel<<<(C * C + NT - 1) / NT, NT>>>(C);

    assoc_kernel<<<1, NT>>>(out, C);

    int NB = NCTA * 8;
    if (NB > (P + 1) / 2) NB = (P + 1) / 2;
    merge_masks_kernel<<<NB, NT>>>(M, out_masks, P, C);
    merge_cls_kernel<<<C, NT>>>(cls, out_cls, C, NC);
}

// round 8
// speedup vs baseline: 2.1895x; 1.2554x over previous
#include <cuda_runtime.h>
#include <cuda_bf16.h>
#include <cstdint>

#define MAXC  256
#define NT    256
#define NCTA  148
#define NTG   320          // 10 warps: one 64x64 subtile each
#define LKC   16           // k-rows per chunk (register-prefetched)
#define TSTR  24           // T row stride in bf16 (12 words: conflict-free frags)
#define RTILE 16           // rows per merge tile

// ---------------- device scratch (no allocations allowed) ----------------
__device__ float d_G[MAXC * MAXC];     // gram (stride MAXC)
__device__ float d_s[MAXC];            // column sums
__device__ float d_p[MAXC * MAXC];     // layernormed cls_logits (stride NC)
__device__ float d_sim[MAXC * MAXC];   // p @ p^T (stride MAXC)
__device__ int   d_gstart[MAXC + 1];   // group member offsets
__device__ int   d_members[MAXC];      // member lists sorted by group
__device__ int   d_colmap[MAXC];       // valid-group-first column permutation
__device__ float d_part[(size_t)NCTA * 10 * 4096];  // split-K partials (~24MB)
__device__ float d_scol[(size_t)NCTA * MAXC];       // per-CTA colsum partials

// ---------------- kernel 1: layernorm rows of cls_logits ----------------
__global__ void ln_kernel(const float* __restrict__ cls, int C, int NC) {
    __shared__ float red[4];
    int i = blockIdx.x;
    const float* x = cls + (size_t)i * NC;
    int t = threadIdx.x, lane = t & 31, w = t >> 5;
    float s = 0.f;
    for (int k = t; k < NC; k += 128) s += __ldg(x + k);
#pragma unroll
    for (int o = 16; o; o >>= 1) s += __shfl_xor_sync(~0u, s, o);
    if (!lane) red[w] = s;
    __syncthreads();
    float mu = (red[0] + red[1] + red[2] + red[3]) / (float)NC;
    __syncthreads();
    float v = 0.f;
    for (int k = t; k < NC; k += 128) { float d = __ldg(x + k) - mu; v += d * d; }
#pragma unroll
    for (int o = 16; o; o >>= 1) v += __shfl_xor_sync(~0u, v, o);
    if (!lane) red[w] = v;
    __syncthreads();
    float var = (red[0] + red[1] + red[2] + red[3]) / (float)NC;
    float inv = 1.0f / sqrtf(var + 1e-5f);
    for (int k = t; k < NC; k += 128)
        d_p[(size_t)i * NC + k] = (__ldg(x + k) - mu) * inv;
}

// ---------------- kernel 2: sim = p @ p^T ----------------
__global__ void sim_kernel(int C, int NC) {
    extern __shared__ float ps[];
    int i = blockIdx.x;
    for (int k = threadIdx.x; k < NC; k += NT) ps[k] = d_p[(size_t)i * NC + k];
    __syncthreads();
    int j = threadIdx.x;
    if (j < C) {
        const float* pj = d_p + (size_t)j * NC;
        float acc = 0.f;
        for (int k = 0; k < NC; k++) acc = fmaf(ps[k], pj[k], acc);
        d_sim[i * MAXC + j] = acc;
    }
}

// ---------------- kernel 3: gram = M^T M via mma.sync bf16 --------------
__device__ __forceinline__ void mma16816(float* d, const uint32_t* a, const uint32_t* b) {
    asm volatile(
        "mma.sync.aligned.m16n8k16.row.col.f32.bf16.bf16.f32 "
        "{%0,%1,%2,%3}, {%4,%5,%6,%7}, {%8,%9}, {%0,%1,%2,%3};"
        : "+f"(d[0]), "+f"(d[1]), "+f"(d[2]), "+f"(d[3])
        : "r"(a[0]), "r"(a[1]), "r"(a[2]), "r"(a[3]), "r"(b[0]), "r"(b[1]));
}

__global__ __launch_bounds__(NTG, 1)
void gram_mma_kernel(const float* __restrict__ M, int P, int C, int Lk) {
    __shared__ __nv_bfloat16 T[256 * TSTR];

    int tid = threadIdx.x, wid = tid >> 5, lane = tid & 31;
    int gid = lane >> 2, tig = lane & 3;

    const unsigned char TIa[10] = {0,0,0,0,1,1,1,2,2,3};
    const unsigned char TJa[10] = {0,1,2,3,1,2,3,2,3,3};
    int ti = TIa[wid], tj = TJa[wid];

    float acc[4][8][4];
#pragma unroll
    for (int mb = 0; mb < 4; mb++)
#pragma unroll
        for (int nb = 0; nb < 8; nb++)
#pragma unroll
            for (int q = 0; q < 4; q++) acc[mb][nb][q] = 0.f;

    size_t kbeg = (size_t)blockIdx.x * (size_t)Lk;
    size_t kend = kbeg + (size_t)Lk;
    if (kend > (size_t)P) kend = (size_t)P;

    bool cv = (tid < C);
    float colsum = 0.f;

    if (!cv && tid < 256) {
        uint2* zr = (uint2*)&T[tid * TSTR];
#pragma unroll
        for (int j = 0; j < 6; j++) zr[j] = make_uint2(0u, 0u);
    }

    const float* basep = M + tid;
    int nch = (kend > kbeg) ? (int)((kend - kbeg + LKC - 1) / LKC) : 0;

    float pf[LKC];
    if (cv && nch > 0) {
#pragma unroll
        for (int i = 0; i < LKC; i++) {
            size_t p = kbeg + (size_t)i;
            pf[i] = (p < kend) ? __ldg(basep + p * (size_t)C) : 0.f;
        }
    }

    for (int chi = 0; chi < nch; chi++) {
        if (cv) {
            uint32_t pk[8];
#pragma unroll
            for (int j = 0; j < 8; j++) {
                float a = pf[2 * j], b = pf[2 * j + 1];
                colsum += a + b;
                asm("cvt.rn.satfinite.bf16x2.f32 %0, %1, %2;" : "=r"(pk[j]) : "f"(b), "f"(a));
            }
            uint2* Tw = (uint2*)&T[tid * TSTR];
#pragma unroll
            for (int j = 0; j < 4; j++) Tw[j] = make_uint2(pk[2 * j], pk[2 * j + 1]);
        }
        __syncthreads();

        if (cv && chi + 1 < nch) {
            size_t nk = kbeg + (size_t)(chi + 1) * LKC;
#pragma unroll
            for (int i = 0; i < LKC; i++) {
                size_t p = nk + (size_t)i;
                pf[i] = (p < kend) ? __ldg(basep + p * (size_t)C) : 0.f;
            }
        }

        {
            uint32_t a[4][4], b[8][2];
            int klo = tig * 2, khi = 8 + tig * 2;
#pragma unroll
            for (int mb = 0; mb < 4; mb++) {
                int r0 = ti * 64 + mb * 16 + gid;
                a[mb][0] = *(const uint32_t*)&T[r0 * TSTR + klo];
                a[mb][1] = *(const uint32_t*)&T[(r0 + 8) * TSTR + klo];
                a[mb][2] = *(const uint32_t*)&T[r0 * TSTR + khi];
                a[mb][3] = *(const uint32_t*)&T[(r0 + 8) * TSTR + khi];
            }
#pragma unroll
            for (int nb = 0; nb < 8; nb++) {
                int n0 = tj * 64 + nb * 8 + gid;
                b[nb][0] = *(const uint32_t*)&T[n0 * TSTR + klo];
                b[nb][1] = *(const uint32_t*)&T[n0 * TSTR + khi];
            }
#pragma unroll
            for (int mb = 0; mb < 4; mb++)
#pragma unroll
                for (int nb = 0; nb < 8; nb++)
                    mma16816(acc[mb][nb], a[mb], b[nb]);
        }
        __syncthreads();
    }

    if (tid < MAXC) d_scol[(size_t)blockIdx.x * MAXC + tid] = cv ? colsum : 0.f;

    float* dst = d_part + ((size_t)blockIdx.x * 10 + wid) * 4096;
#pragma unroll
    for (int mb = 0; mb < 4; mb++) {
        int r = mb * 16 + gid;
#pragma unroll
        for (int nb = 0; nb < 8; nb++) {
            int cb = nb * 8 + tig * 2;
            *(float2*)(dst + r * 64 + cb)       = make_float2(acc[mb][nb][0], acc[mb][nb][1]);
            *(float2*)(dst + (r + 8) * 64 + cb) = make_float2(acc[mb][nb][2], acc[mb][nb][3]);
        }
    }
}

// ---------------- kernel 4: reduce split-K partials into d_G + d_s ------
__global__ void reduce_gram_kernel(int C) {
    int idx = blockIdx.x * NT + threadIdx.x;
    if (idx < C) {
        float a = 0.f;
#pragma unroll 16
        for (int cta = 0; cta < NCTA; cta++) a += d_scol[(size_t)cta * MAXC + idx];
        d_s[idx] = a;
    }
    if (idx >= C * C) return;
    int i = idx / C, j = idx - (idx / C) * C;
    int ti = i >> 6, tj = j >> 6, m, n;
    if (ti <= tj) { m = i & 63; n = j & 63; }
    else { int t = ti; ti = tj; tj = t; m = j & 63; n = i & 63; }
    int st = ti * 4 - (ti * (ti + 1)) / 2 + tj;
    const float* src = d_part + (size_t)st * 4096 + m * 64 + n;
    float acc = 0.f;
#pragma unroll 16
    for (int cta = 0; cta < NCTA; cta++) acc += src[(size_t)cta * 10 * 4096];
    d_G[i * MAXC + j] = acc;
}

// ---------------- kernel 5: greedy association + group build ------------
__global__ void assoc_kernel(float* __restrict__ out, int C) {
    __shared__ unsigned cw[MAXC * (MAXC / 32)];
    __shared__ unsigned aw[MAXC / 32];
    __shared__ int lab[MAXC];
    __shared__ int cnt[MAXC];
    __shared__ int gs[MAXC + 1];
    __shared__ int mem[MAXC];
    int tid = threadIdx.x;
    int nw  = (C + 31) >> 5;

    for (int t = tid; t < MAXC * (MAXC / 32); t += NT) cw[t] = 0u;
    if (tid < MAXC) lab[tid] = -1;
    if (tid < (MAXC / 32)) aw[tid] = 0u;
    __syncthreads();

    for (int idx = tid; idx < C * C; idx += NT) {
        int i = idx / C, j = idx - i * C;
        if (d_sim[i * MAXC + j] > 0.5f) {
            int lo = i < j ? i : j, hi = i < j ? j : i;
            if (2.f * d_G[lo * MAXC + hi] > 0.4f * (d_s[i] + d_s[j]))
                atomicOr(&cw[i * (MAXC / 32) + (j >> 5)], 1u << (j & 31));
        }
    }
    __syncthreads();

    if (tid < 32) {
        int l = tid;
        for (int i = 0; i < C; i++) {
            bool skip = (aw[i >> 5] >> (i & 31)) & 1u;
            if (!skip && l < nw) {
                unsigned take = cw[i * (MAXC / 32) + l] & ~aw[l];
                if (take) {
                    unsigned t2 = take;
                    while (t2) { int b = __ffs(t2) - 1; lab[l * 32 + b] = i; t2 &= t2 - 1; }
                    aw[l] |= take;
                }
            }
            __syncwarp();
        }
    }
    __syncthreads();

    if (tid < C) {
        int c0 = 0;
        for (int j = 0; j < C; j++) if (lab[j] == tid) c0++;
        cnt[tid] = c0;
    }
    __syncthreads();
    if (tid == 0) {
        gs[0] = 0;
        for (int g = 0; g < C; g++) gs[g + 1] = gs[g] + cnt[g];
        int pos = 0;
        for (int g = 0; g < C; g++) if (cnt[g] > 0) d_colmap[pos++] = g;
        for (int g = 0; g < C; g++) if (cnt[g] == 0) d_colmap[pos++] = g;
    }
    __syncthreads();
    if (tid < C) {
        int pos = gs[tid];
        for (int j = 0; j < C; j++) if (lab[j] == tid) mem[pos++] = j;
        out[tid]     = (float)lab[tid];
        out[C + tid] = cnt[tid] > 0 ? 1.f : 0.f;
        d_gstart[tid] = gs[tid];
        if (tid == 0) d_gstart[C] = gs[C];
    }
    __syncthreads();
    int total = gs[C];
    for (int m = tid; m < total; m += NT) d_members[m] = mem[m];
}

// ---------------- kernel 6: per-group segment-max over mask columns -----
// 16-row tiles staged through smem: coalesced LDG in, packed-valid threads
// gather from smem, coalesced STG out with zero-fill for invalid columns.
__global__ void merge_masks_kernel(const float* __restrict__ M, float* __restrict__ dst,
                                   int P, int C) {
    __shared__ float Ms[RTILE * MAXC];
    __shared__ float Os[RTILE * MAXC];
    __shared__ int   mem[MAXC];
    __shared__ int   gs[MAXC + 1];

    int t = threadIdx.x;
    for (int k = t; k < C; k += NT) mem[k] = d_members[k];
    for (int k = t; k <= C; k += NT) gs[k] = d_gstart[k];

    int g = -1, beg = 0, end = 0;
    if (t < C) {
        g   = d_colmap[t];
        beg = d_gstart[g];
        end = d_gstart[g + 1];
    }

    size_t base = (size_t)blockIdx.x * RTILE;
    int nr = (int)(((size_t)P - base) < RTILE ? ((size_t)P - base) : RTILE);
    int tot = nr * C;
    const float* src = M + base * C;

    // phase 1: coalesced tile load
    for (int idx = t; idx < tot; idx += NT) {
        int r = idx / C, c = idx - r * C;
        Ms[r * MAXC + c] = src[idx];
    }
    __syncthreads();

    // phase 2: packed-valid gather (smem only)
    if (t < C && end > beg) {
        float v[RTILE];
#pragma unroll
        for (int r = 0; r < RTILE; r++) v[r] = 0.f;
        for (int m = beg; m < end; m++) {
            int cc = mem[m];
#pragma unroll
            for (int r = 0; r < RTILE; r++)
                v[r] = fmaxf(v[r], Ms[r * MAXC + cc]);
        }
#pragma unroll
        for (int r = 0; r < RTILE; r++) Os[r * MAXC + g] = v[r];
    }
    __syncthreads();

    // phase 3: coalesced store, zero-fill invalid columns
    float* dstp = dst + base * C;
    for (int idx = t; idx < tot; idx += NT) {
        int r = idx / C, c = idx - r * C;
        dstp[idx] = (gs[c + 1] > gs[c]) ? Os[r * MAXC + c] : 0.f;
    }
}

// ---------------- kernel 7: per-group segment-max over cls rows ---------
__global__ void merge_cls_kernel(const float* __restrict__ cls, float* __restrict__ outc,
                                 int C, int NC) {
    int g = blockIdx.x;
    int beg = d_gstart[g], end = d_gstart[g + 1];
    for (int k = threadIdx.x; k < NC; k += NT) {
        float v = 0.f;
        if (end > beg) {
            v = cls[(size_t)d_members[beg] * NC + k];
            for (int m = beg + 1; m < end; m++)
                v = fmaxf(v, cls[(size_t)d_members[m] * NC + k]);
        }
        outc[(size_t)g * NC + k] = v;
    }
}

// ---------------- host ----------------
extern "C" void kernel_launch(void* const* d_in, const int* in_sizes, int n_in,
                              void* d_out, int out_size) {
    const float* M   = (const float*)d_in[0];   // [P, C]
    const float* cls = (const float*)d_in[1];   // [C, NC]
    int C  = in_sizes[2];
    int NC = in_sizes[1] / C;
    int P  = in_sizes[0] / C;

    float* out       = (float*)d_out;
    float* out_masks = out + 2 * (size_t)C;
    float* out_cls   = out_masks + (size_t)P * C;

    ln_kernel<<<C, 128>>>(cls, C, NC);
    sim_kernel<<<C, NT, NC * sizeof(float)>>>(C, NC);

    int Lk = ((P + NCTA - 1) / NCTA + LKC - 1) & ~(LKC - 1);
    gram_mma_kernel<<<NCTA, NTG>>>(M, P, C, Lk);
    reduce_gram_kernel<<<(C * C + NT - 1) / NT, NT>>>(C);

    assoc_kernel<<<1, NT>>>(out, C);

    int NB = (P + RTILE - 1) / RTILE;
    merge_masks_kernel<<<NB, NT>>>(M, out_masks, P, C);
    merge_cls_kernel<<<C, NT>>>(cls, out_cls, C, NC);
}